// round 14
// baseline (speedup 1.0000x reference)
#include <cuda_runtime.h>
#include <cuda_bf16.h>
#include <cuda_fp16.h>
#include <math.h>
#include <stdint.h>

// ---------------- Problem constants ----------------
#define BB   2
#define TT   1024
#define CC   768
#define HH   12
#define HD   64
#define LL   12
#define VV   50257
#define MM   (BB * TT)        // 2048 rows
#define LOG2E 1.4426950408889634f

// ---------------- Scratch (static device globals) ----------------
__device__ float g_x  [MM * CC];
__device__ float g_q  [MM * CC];                 // Q fp32 [B,T,C]
__device__ __align__(16) half g_kh[BB * HH * TT * HD];   // K hi [B,H,T,64]
__device__ __align__(16) half g_kl[BB * HH * TT * HD];
__device__ __align__(16) half g_vh[BB * HH * TT * HD];
__device__ __align__(16) half g_vl[BB * HH * TT * HD];
__device__ __align__(16) half g_ah[MM * CC];
__device__ __align__(16) half g_al[MM * CC];
__device__ __align__(16) half g_fh[MM * 4 * CC];
__device__ __align__(16) half g_fl[MM * 4 * CC];
// transposed weights, [N][K] K-major per layer, fp16 hi/lo split
__device__ __align__(16) half g_wqkv_h[LL * 3 * CC * CC];
__device__ __align__(16) half g_wqkv_l[LL * 3 * CC * CC];
__device__ __align__(16) half g_wproj_h[LL * CC * CC];
__device__ __align__(16) half g_wproj_l[LL * CC * CC];
__device__ __align__(16) half g_wfc_h [LL * 4 * CC * CC];
__device__ __align__(16) half g_wfc_l [LL * 4 * CC * CC];
__device__ __align__(16) half g_wfc2_h[LL * 4 * CC * CC];
__device__ __align__(16) half g_wfc2_l[LL * 4 * CC * CC];
// embedding table as fp16 (logits GEMM B operand, hi only)
__device__ __align__(16) half g_emb_h [VV * CC];

// ---------------- PTX helpers ----------------
__device__ __forceinline__ uint32_t smem_u32(const void* p) {
    uint32_t a;
    asm("{ .reg .u64 t; cvta.to.shared.u64 t, %1; cvt.u32.u64 %0, t; }"
        : "=r"(a) : "l"(p));
    return a;
}
__device__ __forceinline__ void cp16(uint32_t dst, const void* src, int srcsize) {
    asm volatile("cp.async.cg.shared.global [%0], [%1], 16, %2;"
                 :: "r"(dst), "l"(src), "r"(srcsize) : "memory");
}
__device__ __forceinline__ void ldm4(uint32_t r[4], uint32_t a) {
    asm volatile("ldmatrix.sync.aligned.m8n8.x4.shared.b16 {%0,%1,%2,%3}, [%4];"
                 : "=r"(r[0]), "=r"(r[1]), "=r"(r[2]), "=r"(r[3]) : "r"(a));
}
__device__ __forceinline__ void ldm4t(uint32_t r[4], uint32_t a) {
    asm volatile("ldmatrix.sync.aligned.m8n8.x4.trans.shared.b16 {%0,%1,%2,%3}, [%4];"
                 : "=r"(r[0]), "=r"(r[1]), "=r"(r[2]), "=r"(r[3]) : "r"(a));
}
__device__ __forceinline__ void mma16816h(float d[4], const uint32_t a[4],
                                          const uint32_t b[2]) {
    asm volatile(
        "mma.sync.aligned.m16n8k16.row.col.f32.f16.f16.f32 "
        "{%0,%1,%2,%3}, {%4,%5,%6,%7}, {%8,%9}, {%0,%1,%2,%3};"
        : "+f"(d[0]), "+f"(d[1]), "+f"(d[2]), "+f"(d[3])
        : "r"(a[0]), "r"(a[1]), "r"(a[2]), "r"(a[3]), "r"(b[0]), "r"(b[1]));
}
__device__ __forceinline__ float ex2(float x) {
    float y; asm("ex2.approx.ftz.f32 %0, %1;" : "=f"(y) : "f"(x)); return y;
}
__device__ __forceinline__ void pack_hl16(float f0, float f1, uint32_t& h, uint32_t& l) {
    half2 hv = __floats2half2_rn(f0, f1);
    half2 lv = __floats2half2_rn(f0 - __low2float(hv), f1 - __high2float(hv));
    h = *(uint32_t*)&hv; l = *(uint32_t*)&lv;
}

// ---------------- Prep: weight transpose/convert + embedding (one launch) --
__global__ __launch_bounds__(256)
void prep_all(const float* __restrict__ wq, const float* __restrict__ wp,
              const float* __restrict__ wf, const float* __restrict__ w2,
              half* __restrict__ qh, half* __restrict__ ql,
              half* __restrict__ ph, half* __restrict__ pl,
              half* __restrict__ fh, half* __restrict__ fl,
              half* __restrict__ h2, half* __restrict__ l2,
              const int* __restrict__ idx, const float* __restrict__ tok,
              const float* __restrict__ pos, float* __restrict__ x) {
    int z = blockIdx.z;
    if (z == LL * 4) {   // embedding job
        int id = blockIdx.y * 96 + blockIdx.x;
        if (id >= MM * CC / 256) return;
        int i = id * 256 + threadIdx.x;
        int c  = i % CC;
        int mt = i / CC;
        int t  = mt % TT;
        x[i] = tok[(long)idx[mt] * CC + c] + pos[t * CC + c];
        return;
    }
    int l = z >> 2, t = z & 3;
    int K = (t == 3) ? 4 * CC : CC;
    int N = (t == 0) ? 3 * CC : (t == 2) ? 4 * CC : CC;
    int n0 = blockIdx.x * 32, k0 = blockIdx.y * 32;
    if (n0 >= N || k0 >= K) return;
    const float* W;
    half *oh, *ol;
    if      (t == 0) { W = wq; oh = qh; ol = ql; }
    else if (t == 1) { W = wp; oh = ph; ol = pl; }
    else if (t == 2) { W = wf; oh = fh; ol = fl; }
    else             { W = w2; oh = h2; ol = l2; }
    long lofs = (long)l * K * N;

    __shared__ float tl[32][33];
    int tx = threadIdx.x & 31, ty = threadIdx.x >> 5;
    #pragma unroll
    for (int r = 0; r < 32; r += 8)
        tl[ty + r][tx] = W[lofs + (long)(k0 + ty + r) * N + n0 + tx];
    __syncthreads();
    #pragma unroll
    for (int r = 0; r < 32; r += 8) {
        int n = n0 + ty + r, k = k0 + tx;
        float v = tl[tx][ty + r];
        half h = __float2half_rn(v);
        long o = lofs + (long)n * K + k;
        oh[o] = h;
        ol[o] = __float2half_rn(v - __half2float(h));
    }
}

// ---------------- fp32 -> fp16 (hi only), float4 vectorized --------------
__global__ void cvt_act4h(const float4* __restrict__ in,
                          uint2* __restrict__ hi, int n4) {
    int i = blockIdx.x * blockDim.x + threadIdx.x;
    if (i >= n4) return;
    float4 v = in[i];
    half2 a = __floats2half2_rn(v.x, v.y);
    half2 b = __floats2half2_rn(v.z, v.w);
    hi[i] = make_uint2(*(uint32_t*)&a, *(uint32_t*)&b);
}

// ---------------- LayerNorm, warp-per-row -> fp16 hi/lo ----------------
__global__ __launch_bounds__(256)
void ln_kernel(const float* __restrict__ in,
               half* __restrict__ oh, half* __restrict__ ol,
               const float* __restrict__ w, const float* __restrict__ b) {
    int warp = threadIdx.x >> 5, lane = threadIdx.x & 31;
    int row = blockIdx.x * 8 + warp;
    const float* p = in + (long)row * CC;
    float4 v[6];
    float s = 0.f, s2 = 0.f;
    #pragma unroll
    for (int k = 0; k < 6; k++) {
        v[k] = *(const float4*)(p + lane * 4 + k * 128);
        s  += v[k].x + v[k].y + v[k].z + v[k].w;
        s2 += v[k].x * v[k].x + v[k].y * v[k].y + v[k].z * v[k].z + v[k].w * v[k].w;
    }
    #pragma unroll
    for (int o = 16; o > 0; o >>= 1) {
        s  += __shfl_xor_sync(0xffffffffu, s,  o);
        s2 += __shfl_xor_sync(0xffffffffu, s2, o);
    }
    float mean = s * (1.0f / CC);
    float var  = s2 * (1.0f / CC) - mean * mean;
    float inv  = rsqrtf(var + 1e-5f);
    #pragma unroll
    for (int k = 0; k < 6; k++) {
        int c = lane * 4 + k * 128;
        float4 wv = *(const float4*)(w + c);
        float4 bv = *(const float4*)(b + c);
        float o0 = (v[k].x - mean) * inv * wv.x + bv.x;
        float o1 = (v[k].y - mean) * inv * wv.y + bv.y;
        float o2 = (v[k].z - mean) * inv * wv.z + bv.z;
        float o3 = (v[k].w - mean) * inv * wv.w + bv.w;
        uint32_t ha, la, hb, lb;
        pack_hl16(o0, o1, ha, la);
        pack_hl16(o2, o3, hb, lb);
        long ofs = (long)row * CC + c;
        *(uint2*)(oh + ofs) = make_uint2(ha, hb);
        *(uint2*)(ol + ofs) = make_uint2(la, lb);
    }
}

// ---------------- LayerNorm -> fp16 hi only (final LN) ----------------
__global__ __launch_bounds__(256)
void ln_kernel_h(const float* __restrict__ in,
                 half* __restrict__ oh,
                 const float* __restrict__ w, const float* __restrict__ b) {
    int warp = threadIdx.x >> 5, lane = threadIdx.x & 31;
    int row = blockIdx.x * 8 + warp;
    const float* p = in + (long)row * CC;
    float4 v[6];
    float s = 0.f, s2 = 0.f;
    #pragma unroll
    for (int k = 0; k < 6; k++) {
        v[k] = *(const float4*)(p + lane * 4 + k * 128);
        s  += v[k].x + v[k].y + v[k].z + v[k].w;
        s2 += v[k].x * v[k].x + v[k].y * v[k].y + v[k].z * v[k].z + v[k].w * v[k].w;
    }
    #pragma unroll
    for (int o = 16; o > 0; o >>= 1) {
        s  += __shfl_xor_sync(0xffffffffu, s,  o);
        s2 += __shfl_xor_sync(0xffffffffu, s2, o);
    }
    float mean = s * (1.0f / CC);
    float var  = s2 * (1.0f / CC) - mean * mean;
    float inv  = rsqrtf(var + 1e-5f);
    #pragma unroll
    for (int k = 0; k < 6; k++) {
        int c = lane * 4 + k * 128;
        float4 wv = *(const float4*)(w + c);
        float4 bv = *(const float4*)(b + c);
        float o0 = (v[k].x - mean) * inv * wv.x + bv.x;
        float o1 = (v[k].y - mean) * inv * wv.y + bv.y;
        float o2 = (v[k].z - mean) * inv * wv.z + bv.z;
        float o3 = (v[k].w - mean) * inv * wv.w + bv.w;
        half2 a = __floats2half2_rn(o0, o1);
        half2 bq = __floats2half2_rn(o2, o3);
        long ofs = (long)row * CC + c;
        *(uint2*)(oh + ofs) = make_uint2(*(uint32_t*)&a, *(uint32_t*)&bq);
    }
}

// ---------------- Flash attention on tensor cores (split-fp16 3-pass) ----
#define ASTRIDE 144           // 72 elems per row (conflict-free ldmatrix)
#define TILE_B9 9216          // 64 * 144
#define ASTG    (4 * TILE_B9) // K_H,K_L,V_H,V_L per stage
#define ATT_SMEM (2 * ASTG)   // 73728

__global__ __launch_bounds__(128)
void attn_mma(const float* __restrict__ q,
              const half* __restrict__ kh, const half* __restrict__ kl,
              const half* __restrict__ vh, const half* __restrict__ vl,
              half* __restrict__ yh, half* __restrict__ yl) {
    extern __shared__ __align__(16) char sm[];
    uint32_t sb = smem_u32(sm);
    const uint32_t K_H = 0, K_L = TILE_B9, V_H = 2 * TILE_B9, V_L = 3 * TILE_B9;

    int qt = 15 - blockIdx.x;          // LPT: heavy tiles first
    int h = blockIdx.y, b = blockIdx.z;
    int tid = threadIdx.x, w = tid >> 5, lane = tid & 31;
    int q0 = qt * 64;
    const long kvofs = ((long)(b * HH + h) * TT) * HD;

    {
        int r = tid >> 1, d0 = (tid & 1) * 32;
        const float* qp = q + ((long)b * TT + q0 + r) * CC + h * HD + d0;
        const float qs = 0.125f * LOG2E;
        #pragma unroll
        for (int i = 0; i < 8; i++) {
            float4 v = *(const float4*)(qp + i * 4);
            uint32_t h0, l0, h1, l1;
            pack_hl16(v.x * qs, v.y * qs, h0, l0);
            pack_hl16(v.z * qs, v.w * qs, h1, l1);
            uint32_t o = r * ASTRIDE + (d0 + 4 * i) * 2;
            *(uint32_t*)(sm + K_H + o)     = h0;
            *(uint32_t*)(sm + K_H + o + 4) = h1;
            *(uint32_t*)(sm + K_L + o)     = l0;
            *(uint32_t*)(sm + K_L + o + 4) = l1;
        }
    }
    __syncthreads();
    uint32_t qh[4][4], ql[4][4];
    {
        uint32_t ao = (uint32_t)((w * 16 + (lane & 15)) * ASTRIDE + ((lane >> 4) << 4));
        #pragma unroll
        for (int kt = 0; kt < 4; kt++) {
            ldm4(qh[kt], sb + K_H + ao + kt * 32);
            ldm4(ql[kt], sb + K_L + ao + kt * 32);
        }
    }
    __syncthreads();

    int mat = lane >> 3;
    uint32_t bo = (uint32_t)((((mat >> 1) << 3) + (lane & 7)) * ASTRIDE + ((mat & 1) << 4));
    uint32_t vbo = (uint32_t)((((mat & 1) << 3) + (lane & 7)) * ASTRIDE + (((mat >> 1) << 3) << 1));

    auto load_tile = [&](int s, int c) {
        uint32_t st = sb + s * ASTG;
        long gb = kvofs + (long)c * 64 * HD;
        #pragma unroll
        for (int ch = tid; ch < 512; ch += 128) {
            int row = ch >> 3, c8 = ch & 7;
            uint32_t d = st + row * ASTRIDE + c8 * 16;
            long g = gb + row * HD + c8 * 8;
            cp16(d + K_H, kh + g, 16);
            cp16(d + K_L, kl + g, 16);
            cp16(d + V_H, vh + g, 16);
            cp16(d + V_L, vl + g, 16);
        }
    };

    float o_[8][4];
    #pragma unroll
    for (int nt = 0; nt < 8; nt++)
        #pragma unroll
        for (int e = 0; e < 4; e++) o_[nt][e] = 0.f;
    float m0r = -1e30f, m1r = -1e30f, l0s = 0.f, l1s = 0.f;

    load_tile(0, 0);
    asm volatile("cp.async.commit_group;" ::: "memory");
    if (qt >= 1) {
        load_tile(1, 1);
        asm volatile("cp.async.commit_group;" ::: "memory");
    }

    for (int kt0 = 0; kt0 <= qt; kt0++) {
        if (kt0 < qt)
            asm volatile("cp.async.wait_group 1;" ::: "memory");
        else
            asm volatile("cp.async.wait_group 0;" ::: "memory");
        __syncthreads();
        uint32_t st = sb + (kt0 & 1) * ASTG;

        float s[8][4];
        #pragma unroll
        for (int nt = 0; nt < 8; nt++)
            #pragma unroll
            for (int e = 0; e < 4; e++) s[nt][e] = 0.f;
        #pragma unroll
        for (int kt = 0; kt < 4; kt++) {
            #pragma unroll
            for (int jp = 0; jp < 4; jp++) {
                uint32_t t0[4], t1[4];
                uint32_t off = bo + kt * 32 + jp * (16 * ASTRIDE);
                ldm4(t0, st + K_H + off);
                ldm4(t1, st + K_L + off);
                uint32_t b0h[2] = {t0[0], t0[1]}, b1h[2] = {t0[2], t0[3]};
                uint32_t b0l[2] = {t1[0], t1[1]}, b1l[2] = {t1[2], t1[3]};
                mma16816h(s[2 * jp],     qh[kt], b0h);
                mma16816h(s[2 * jp],     qh[kt], b0l);
                mma16816h(s[2 * jp],     ql[kt], b0h);
                mma16816h(s[2 * jp + 1], qh[kt], b1h);
                mma16816h(s[2 * jp + 1], qh[kt], b1l);
                mma16816h(s[2 * jp + 1], ql[kt], b1h);
            }
        }

        if (kt0 == qt) {
            int rl0 = w * 16 + (lane >> 2);
            #pragma unroll
            for (int nt = 0; nt < 8; nt++) {
                int c = nt * 8 + (lane & 3) * 2;
                if (c > rl0)     s[nt][0] = -1e30f;
                if (c + 1 > rl0) s[nt][1] = -1e30f;
                if (c > rl0 + 8)     s[nt][2] = -1e30f;
                if (c + 1 > rl0 + 8) s[nt][3] = -1e30f;
            }
        }

        float mx0 = m0r, mx1 = m1r;
        #pragma unroll
        for (int nt = 0; nt < 8; nt++) {
            mx0 = fmaxf(mx0, fmaxf(s[nt][0], s[nt][1]));
            mx1 = fmaxf(mx1, fmaxf(s[nt][2], s[nt][3]));
        }
        mx0 = fmaxf(mx0, __shfl_xor_sync(0xffffffffu, mx0, 1));
        mx0 = fmaxf(mx0, __shfl_xor_sync(0xffffffffu, mx0, 2));
        mx1 = fmaxf(mx1, __shfl_xor_sync(0xffffffffu, mx1, 1));
        mx1 = fmaxf(mx1, __shfl_xor_sync(0xffffffffu, mx1, 2));
        float sc0 = ex2(m0r - mx0), sc1 = ex2(m1r - mx1);
        m0r = mx0; m1r = mx1;
        l0s *= sc0; l1s *= sc1;
        #pragma unroll
        for (int nt = 0; nt < 8; nt++) {
            o_[nt][0] *= sc0; o_[nt][1] *= sc0;
            o_[nt][2] *= sc1; o_[nt][3] *= sc1;
        }
        #pragma unroll
        for (int nt = 0; nt < 8; nt++) {
            s[nt][0] = ex2(s[nt][0] - mx0);
            s[nt][1] = ex2(s[nt][1] - mx0);
            s[nt][2] = ex2(s[nt][2] - mx1);
            s[nt][3] = ex2(s[nt][3] - mx1);
            l0s += s[nt][0] + s[nt][1];
            l1s += s[nt][2] + s[nt][3];
        }

        #pragma unroll
        for (int kt = 0; kt < 4; kt++) {
            uint32_t pah[4], pal[4];
            pack_hl16(s[2 * kt][0],     s[2 * kt][1],     pah[0], pal[0]);
            pack_hl16(s[2 * kt][2],     s[2 * kt][3],     pah[1], pal[1]);
            pack_hl16(s[2 * kt + 1][0], s[2 * kt + 1][1], pah[2], pal[2]);
            pack_hl16(s[2 * kt + 1][2], s[2 * kt + 1][3], pah[3], pal[3]);
            #pragma unroll
            for (int jp = 0; jp < 4; jp++) {
                uint32_t t0[4], t1[4];
                uint32_t off = vbo + kt * (16 * ASTRIDE) + jp * 32;
                ldm4t(t0, st + V_H + off);
                ldm4t(t1, st + V_L + off);
                uint32_t b0h[2] = {t0[0], t0[1]}, b1h[2] = {t0[2], t0[3]};
                uint32_t b0l[2] = {t1[0], t1[1]}, b1l[2] = {t1[2], t1[3]};
                mma16816h(o_[2 * jp],     pah, b0h);
                mma16816h(o_[2 * jp],     pah, b0l);
                mma16816h(o_[2 * jp],     pal, b0h);
                mma16816h(o_[2 * jp + 1], pah, b1h);
                mma16816h(o_[2 * jp + 1], pah, b1l);
                mma16816h(o_[2 * jp + 1], pal, b1h);
            }
        }
        __syncthreads();
        if (kt0 + 2 <= qt) {
            load_tile(kt0 & 1, kt0 + 2);
            asm volatile("cp.async.commit_group;" ::: "memory");
        }
    }

    l0s += __shfl_xor_sync(0xffffffffu, l0s, 1);
    l0s += __shfl_xor_sync(0xffffffffu, l0s, 2);
    l1s += __shfl_xor_sync(0xffffffffu, l1s, 1);
    l1s += __shfl_xor_sync(0xffffffffu, l1s, 2);
    float inv0 = 1.0f / l0s, inv1 = 1.0f / l1s;
    int r0 = q0 + w * 16 + (lane >> 2);
    #pragma unroll
    for (int nt = 0; nt < 8; nt++) {
        int d = nt * 8 + (lane & 3) * 2;
        long o0 = ((long)b * TT + r0) * CC + h * HD + d;
        long o1 = ((long)b * TT + r0 + 8) * CC + h * HD + d;
        uint32_t hv, lv;
        pack_hl16(o_[nt][0] * inv0, o_[nt][1] * inv0, hv, lv);
        *(uint32_t*)(yh + o0) = hv;
        *(uint32_t*)(yl + o0) = lv;
        pack_hl16(o_[nt][2] * inv1, o_[nt][3] * inv1, hv, lv);
        *(uint32_t*)(yh + o1) = hv;
        *(uint32_t*)(yl + o1) = lv;
    }
}

// ---------------- mma.sync split-fp16 GEMM, BK=64, frag double-buffer ----
// EPI: 1 = +bias+residual fp32; 2 = +bias+GELU fp16 hi/lo;
//      3 = QKV split (Q fp32 [B,T,C], K/V fp16 hi/lo [B,H,T,64])
#define A_T64   9216              // 64 * 144
#define B_T64   18432             // 128 * 144
#define STAGE64 (2 * A_T64 + 2 * B_T64)     // 55296
#define GEMM_SMEM (2 * STAGE64)             // 110592

struct Frags {
    uint32_t ah[2][4];
    uint32_t al[2][4];
    uint32_t bh[4][2];
    uint32_t bl[4][2];
};

template<int EPI>
__global__ __launch_bounds__(256, 2)
void mma_gemm(const half* __restrict__ Ah, const half* __restrict__ Al,
              const half* __restrict__ Bh, const half* __restrict__ Bl,
              const float* __restrict__ bias, const float* __restrict__ res,
              float* __restrict__ C, half* __restrict__ Ch, half* __restrict__ Cl,
              half* __restrict__ Dh, half* __restrict__ Dl,
              int Ndim, int Kdim) {
    extern __shared__ char smemraw[];
    uint32_t sb = smem_u32(smemraw);
    int tid = threadIdx.x, w = tid >> 5, lane = tid & 31;
    int m0 = blockIdx.x * 64, n0 = blockIdx.y * 128;
    int wm = w >> 2, wn = w & 3;

    int mat = lane >> 3;
    const uint32_t aoff = (uint32_t)((wm * 32 + (lane & 15)) * 144 + ((lane >> 4) << 4));
    const uint32_t boff = (uint32_t)(2 * A_T64 +
        (wn * 32 + ((mat >> 1) << 3) + (lane & 7)) * 144 + ((mat & 1) << 4));

    float acc[2][4][4];
    #pragma unroll
    for (int i = 0; i < 2; i++)
        #pragma unroll
        for (int j = 0; j < 4; j++)
            #pragma unroll
            for (int r = 0; r < 4; r++) acc[i][j][r] = 0.f;

    auto load_stage = [&](int slot, int c) {
        int k0 = c * 64;
        uint32_t st = sb + slot * STAGE64;
        #pragma unroll
        for (int ch = tid; ch < 512; ch += 256) {
            int row = ch >> 3, c8 = ch & 7;
            const half* gh = Ah + (long)(m0 + row) * Kdim + k0 + c8 * 8;
            const half* gl = Al + (long)(m0 + row) * Kdim + k0 + c8 * 8;
            uint32_t d = st + row * 144 + c8 * 16;
            cp16(d, gh, 16);
            cp16(d + A_T64, gl, 16);
        }
        #pragma unroll
        for (int ch = tid; ch < 1024; ch += 256) {
            int row = ch >> 3, c8 = ch & 7;
            int n = n0 + row;
            int ok = (n < Ndim);
            int nn = ok ? n : 0;
            int ssz = ok ? 16 : 0;
            const half* gh = Bh + (long)nn * Kdim + k0 + c8 * 8;
            const half* gl = Bl + (long)nn * Kdim + k0 + c8 * 8;
            uint32_t d = st + 2 * A_T64 + row * 144 + c8 * 16;
            cp16(d, gh, ssz);
            cp16(d + B_T64, gl, ssz);
        }
    };

    auto ld_frags = [&](Frags& f, uint32_t base, int kk) {
        uint32_t kof = (uint32_t)(kk * 32);
        #pragma unroll
        for (int i = 0; i < 2; i++) {
            uint32_t o = base + aoff + i * (16 * 144) + kof;
            ldm4(f.ah[i], o);
            ldm4(f.al[i], o + A_T64);
        }
        #pragma unroll
        for (int jp = 0; jp < 2; jp++) {
            uint32_t o = base + boff + jp * (16 * 144) + kof;
            uint32_t t0[4], t1[4];
            ldm4(t0, o);
            ldm4(t1, o + B_T64);
            f.bh[2 * jp][0] = t0[0]; f.bh[2 * jp][1] = t0[1];
            f.bh[2 * jp + 1][0] = t0[2]; f.bh[2 * jp + 1][1] = t0[3];
            f.bl[2 * jp][0] = t1[0]; f.bl[2 * jp][1] = t1[1];
            f.bl[2 * jp + 1][0] = t1[2]; f.bl[2 * jp + 1][1] = t1[3];
        }
    };

    auto do_mma = [&](Frags& f) {
        #pragma unroll
        for (int i = 0; i < 2; i++)
            #pragma unroll
            for (int j = 0; j < 4; j++)
                mma16816h(acc[i][j], f.ah[i], f.bh[j]);
        #pragma unroll
        for (int i = 0; i < 2; i++)
            #pragma unroll
            for (int j = 0; j < 4; j++)
                mma16816h(acc[i][j], f.ah[i], f.bl[j]);
        #pragma unroll
        for (int i = 0; i < 2; i++)
            #pragma unroll
            for (int j = 0; j < 4; j++)
                mma16816h(acc[i][j], f.al[i], f.bh[j]);
    };

    const int NC = Kdim >> 6;

    load_stage(0, 0);
    asm volatile("cp.async.commit_group;" ::: "memory");
    load_stage(1, 1);
    asm volatile("cp.async.commit_group;" ::: "memory");
    asm volatile("cp.async.wait_group 1;" ::: "memory");
    __syncthreads();

    Frags fr[2];
    ld_frags(fr[0], sb, 0);

    for (int c = 0; c < NC; c++) {
        uint32_t base = sb + (c & 1) * STAGE64;
        #pragma unroll
        for (int kk = 0; kk < 4; kk++) {
            if (kk < 3) ld_frags(fr[(kk + 1) & 1], base, kk + 1);
            do_mma(fr[kk & 1]);
        }
        __syncthreads();
        if (c + 2 < NC) {
            load_stage(c & 1, c + 2);
            asm volatile("cp.async.commit_group;" ::: "memory");
        }
        if (c + 1 < NC) {
            if (c + 2 < NC)
                asm volatile("cp.async.wait_group 1;" ::: "memory");
            else
                asm volatile("cp.async.wait_group 0;" ::: "memory");
            __syncthreads();
            ld_frags(fr[0], sb + ((c + 1) & 1) * STAGE64, 0);
        }
    }

    if (EPI == 3) {
        // QKV: Q -> fp32 [B,T,C]; K,V -> fp16 hi/lo [B,H,T,64]
        #pragma unroll
        for (int i = 0; i < 2; i++) {
            int row0 = m0 + wm * 32 + i * 16 + (lane >> 2);
            #pragma unroll
            for (int j = 0; j < 4; j++) {
                int col = n0 + wn * 32 + j * 8 + 2 * (lane & 3);
                float b0 = __ldg(bias + col), b1 = __ldg(bias + col + 1);
                int region = col / CC;      // 0=Q, 1=K, 2=V
                int cm = col % CC;
                int hh = cm >> 6, d = cm & 63;
                #pragma unroll
                for (int h2 = 0; h2 < 2; h2++) {
                    int rr = row0 + h2 * 8;
                    float f0 = acc[i][j][h2 * 2] + b0;
                    float f1 = acc[i][j][h2 * 2 + 1] + b1;
                    if (region == 0) {
                        C[(long)rr * CC + cm]     = f0;
                        C[(long)rr * CC + cm + 1] = f1;
                    } else {
                        int bb = rr >> 10, tt = rr & 1023;
                        long o = ((long)(bb * HH + hh) * TT + tt) * HD + d;
                        uint32_t hv, lv;
                        pack_hl16(f0, f1, hv, lv);
                        if (region == 1) {
                            *(uint32_t*)(Ch + o) = hv;
                            *(uint32_t*)(Cl + o) = lv;
                        } else {
                            *(uint32_t*)(Dh + o) = hv;
                            *(uint32_t*)(Dl + o) = lv;
                        }
                    }
                }
            }
        }
        return;
    }

    #pragma unroll
    for (int i = 0; i < 2; i++) {
        int row0 = m0 + wm * 32 + i * 16 + (lane >> 2);
        #pragma unroll
        for (int j = 0; j < 4; j++) {
            int col = n0 + wn * 32 + j * 8 + 2 * (lane & 3);
            #pragma unroll
            for (int r = 0; r < 4; r++) {
                int rr = row0 + (r >> 1) * 8;
                int cc = col + (r & 1);
                if (cc < Ndim) {
                    float v = acc[i][j][r];
                    if (bias) v += __ldg(bias + cc);
                    long o = (long)rr * Ndim + cc;
                    if (EPI == 1) v += res[o];
                    if (EPI == 2) {
                        v = 0.5f * v * (1.f + erff(v * 0.70710678118654752f));
                        half hh = __float2half_rn(v);
                        Ch[o] = hh;
                        Cl[o] = __float2half_rn(v - __half2float(hh));
                    } else {
                        C[o] = v;
                    }
                }
            }
        }
    }
}

// ---------------- fp16 1-pass GEMM (logits only) ----------------
#define STAGE_H1 (A_T64 + B_T64)           // 27648
#define GEMM_SMEM_H1 (2 * STAGE_H1)        // 55296

__global__ __launch_bounds__(256, 2)
void mma_gemm_h1(const half* __restrict__ Ah, const half* __restrict__ Bh,
                 float* __restrict__ C, int Ndim, int Kdim) {
    extern __shared__ char smemraw[];
    uint32_t sb = smem_u32(smemraw);
    int tid = threadIdx.x, w = tid >> 5, lane = tid & 31;
    int m0 = blockIdx.x * 64, n0 = blockIdx.y * 128;
    int wm = w >> 2, wn = w & 3;

    int mat = lane >> 3;
    const uint32_t aoff = (uint32_t)((wm * 32 + (lane & 15)) * 144 + ((lane >> 4) << 4));
    const uint32_t boff = (uint32_t)(A_T64 +
        (wn * 32 + ((mat >> 1) << 3) + (lane & 7)) * 144 + ((mat & 1) << 4));

    float acc[2][4][4];
    #pragma unroll
    for (int i = 0; i < 2; i++)
        #pragma unroll
        for (int j = 0; j < 4; j++)
            #pragma unroll
            for (int r = 0; r < 4; r++) acc[i][j][r] = 0.f;

    auto load_stage = [&](int slot, int c) {
        int k0 = c * 64;
        uint32_t st = sb + slot * STAGE_H1;
        #pragma unroll
        for (int ch = tid; ch < 512; ch += 256) {
            int row = ch >> 3, c8 = ch & 7;
            const half* gh = Ah + (long)(m0 + row) * Kdim + k0 + c8 * 8;
            cp16(st + row * 144 + c8 * 16, gh, 16);
        }
        #pragma unroll
        for (int ch = tid; ch < 1024; ch += 256) {
            int row = ch >> 3, c8 = ch & 7;
            int n = n0 + row;
            int ok = (n < Ndim);
            int nn = ok ? n : 0;
            int ssz = ok ? 16 : 0;
            const half* gh = Bh + (long)nn * Kdim + k0 + c8 * 8;
            cp16(st + A_T64 + row * 144 + c8 * 16, gh, ssz);
        }
    };

    const int NC = Kdim >> 6;

    load_stage(0, 0);
    asm volatile("cp.async.commit_group;" ::: "memory");
    load_stage(1, 1);
    asm volatile("cp.async.commit_group;" ::: "memory");

    for (int c = 0; c < NC; c++) {
        if (c + 1 < NC)
            asm volatile("cp.async.wait_group 1;" ::: "memory");
        else
            asm volatile("cp.async.wait_group 0;" ::: "memory");
        __syncthreads();

        uint32_t base = sb + (c & 1) * STAGE_H1;
        #pragma unroll
        for (int kk = 0; kk < 4; kk++) {
            uint32_t kof = (uint32_t)(kk * 32);
            uint32_t ah[2][4], bh[4][2];
            #pragma unroll
            for (int i = 0; i < 2; i++)
                ldm4(ah[i], base + aoff + i * (16 * 144) + kof);
            #pragma unroll
            for (int jp = 0; jp < 2; jp++) {
                uint32_t t0[4];
                ldm4(t0, base + boff + jp * (16 * 144) + kof);
                bh[2 * jp][0] = t0[0]; bh[2 * jp][1] = t0[1];
                bh[2 * jp + 1][0] = t0[2]; bh[2 * jp + 1][1] = t0[3];
            }
            #pragma unroll
            for (int i = 0; i < 2; i++)
                #pragma unroll
                for (int j = 0; j < 4; j++)
                    mma16816h(acc[i][j], ah[i], bh[j]);
        }
        __syncthreads();
        if (c + 2 < NC) {
            load_stage(c & 1, c + 2);
            asm volatile("cp.async.commit_group;" ::: "memory");
        }
    }

    #pragma unroll
    for (int i = 0; i < 2; i++) {
        int row0 = m0 + wm * 32 + i * 16 + (lane >> 2);
        #pragma unroll
        for (int j = 0; j < 4; j++) {
            int col = n0 + wn * 32 + j * 8 + 2 * (lane & 3);
            #pragma unroll
            for (int r = 0; r < 4; r++) {
                int rr = row0 + (r >> 1) * 8;
                int cc = col + (r & 1);
                if (cc < Ndim)
                    C[(long)rr * Ndim + cc] = acc[i][j][r];
            }
        }
    }
}

// ---------------- Host orchestration ----------------
extern "C" void kernel_launch(void* const* d_in, const int* in_sizes, int n_in,
                              void* d_out, int out_size) {
    const int*   idx     = (const int*)  d_in[0];
    const float* tok_emb = (const float*)d_in[1];
    const float* pos_emb = (const float*)d_in[2];
    const float* ln1_w   = (const float*)d_in[3];
    const float* ln1_b   = (const float*)d_in[4];
    const float* w_qkv   = (const float*)d_in[5];
    const float* b_qkv   = (const float*)d_in[6];
    const float* w_proj  = (const float*)d_in[7];
    const float* b_proj  = (const float*)d_in[8];
    const float* ln2_w   = (const float*)d_in[9];
    const float* ln2_b   = (const float*)d_in[10];
    const float* w_fc    = (const float*)d_in[11];
    const float* b_fc    = (const float*)d_in[12];
    const float* w_fc2   = (const float*)d_in[13];
    const float* b_fc2   = (const float*)d_in[14];
    const float* lnf_w   = (const float*)d_in[15];
    const float* lnf_b   = (const float*)d_in[16];
    float* out = (float*)d_out;

    cudaFuncSetAttribute(mma_gemm<1>, cudaFuncAttributeMaxDynamicSharedMemorySize, GEMM_SMEM);
    cudaFuncSetAttribute(mma_gemm<2>, cudaFuncAttributeMaxDynamicSharedMemorySize, GEMM_SMEM);
    cudaFuncSetAttribute(mma_gemm<3>, cudaFuncAttributeMaxDynamicSharedMemorySize, GEMM_SMEM);
    cudaFuncSetAttribute(mma_gemm_h1, cudaFuncAttributeMaxDynamicSharedMemorySize, GEMM_SMEM_H1);
    cudaFuncSetAttribute(attn_mma,    cudaFuncAttributeMaxDynamicSharedMemorySize, ATT_SMEM);

    float *x, *q;
    cudaGetSymbolAddress((void**)&x, g_x);
    cudaGetSymbolAddress((void**)&q, g_q);
    half *kh, *kl, *vh, *vl, *ah, *al, *fh, *fl;
    half *wqh, *wql, *wph, *wpl, *wfh, *wfl, *w2h, *w2l, *eh;
    cudaGetSymbolAddress((void**)&kh,  g_kh);      cudaGetSymbolAddress((void**)&kl,  g_kl);
    cudaGetSymbolAddress((void**)&vh,  g_vh);      cudaGetSymbolAddress((void**)&vl,  g_vl);
    cudaGetSymbolAddress((void**)&ah,  g_ah);      cudaGetSymbolAddress((void**)&al,  g_al);
    cudaGetSymbolAddress((void**)&fh,  g_fh);      cudaGetSymbolAddress((void**)&fl,  g_fl);
    cudaGetSymbolAddress((void**)&wqh, g_wqkv_h);  cudaGetSymbolAddress((void**)&wql, g_wqkv_l);
    cudaGetSymbolAddress((void**)&wph, g_wproj_h); cudaGetSymbolAddress((void**)&wpl, g_wproj_l);
    cudaGetSymbolAddress((void**)&wfh, g_wfc_h);   cudaGetSymbolAddress((void**)&wfl, g_wfc_l);
    cudaGetSymbolAddress((void**)&w2h, g_wfc2_h);  cudaGetSymbolAddress((void**)&w2l, g_wfc2_l);
    cudaGetSymbolAddress((void**)&eh,  g_emb_h);

    // #1: weight prep + embedding; #2: emb-table fp16 convert
    prep_all<<<dim3(96, 96, LL * 4 + 1), 256>>>(w_qkv, w_proj, w_fc, w_fc2,
                                                wqh, wql, wph, wpl,
                                                wfh, wfl, w2h, w2l,
                                                idx, tok_emb, pos_emb, x);
    {
        int n4 = VV * CC / 4;
        cvt_act4h<<<(n4 + 255) / 256, 256>>>((const float4*)tok_emb,
                                             (uint2*)eh, n4);
    }

    auto gg = [](int N) { return dim3(MM / 64, (N + 127) / 128); };

    for (int l = 0; l < LL; l++) {
        // LN1 -> QKV GEMM: Q fp32, K/V fp16 hi/lo pre-converted
        ln_kernel<<<MM / 8, 256>>>(x, ah, al, ln1_w + (long)l * CC, ln1_b + (long)l * CC);
        mma_gemm<3><<<gg(3 * CC), 256, GEMM_SMEM>>>(
            ah, al, wqh + (long)l * 3 * CC * CC, wql + (long)l * 3 * CC * CC,
            b_qkv + (long)l * 3 * CC, nullptr, q, kh, kl, vh, vl, 3 * CC, CC);
        // attention (tensor-core flash) -> fp16 hi/lo
        attn_mma<<<dim3(16, HH, BB), 128, ATT_SMEM>>>(q, kh, kl, vh, vl, ah, al);
        // proj + residual -> x
        mma_gemm<1><<<gg(CC), 256, GEMM_SMEM>>>(
            ah, al, wph + (long)l * CC * CC, wpl + (long)l * CC * CC,
            b_proj + (long)l * CC, x, x, nullptr, nullptr, nullptr, nullptr, CC, CC);
        // LN2 -> FC1 + GELU -> fp16 hi/lo
        ln_kernel<<<MM / 8, 256>>>(x, ah, al, ln2_w + (long)l * CC, ln2_b + (long)l * CC);
        mma_gemm<2><<<gg(4 * CC), 256, GEMM_SMEM>>>(
            ah, al, wfh + (long)l * 4 * CC * CC, wfl + (long)l * 4 * CC * CC,
            b_fc + (long)l * 4 * CC, nullptr, nullptr, fh, fl, nullptr, nullptr, 4 * CC, CC);
        // FC2 + residual -> x
        mma_gemm<1><<<gg(CC), 256, GEMM_SMEM>>>(
            fh, fl, w2h + (long)l * 4 * CC * CC, w2l + (long)l * 4 * CC * CC,
            b_fc2 + (long)l * CC, x, x, nullptr, nullptr, nullptr, nullptr, CC, 4 * CC);
    }

    // final LN (fp16 hi only) + tied head via fp16 1-pass GEMM
    ln_kernel_h<<<MM / 8, 256>>>(x, (half*)ah, lnf_w, lnf_b);
    mma_gemm_h1<<<gg(VV), 256, GEMM_SMEM_H1>>>(
        (half*)ah, eh, out, VV, CC);
}

// round 16
// speedup vs baseline: 1.0308x; 1.0308x over previous
#include <cuda_runtime.h>
#include <cuda_bf16.h>
#include <cuda_fp16.h>
#include <math.h>
#include <stdint.h>

// ---------------- Problem constants ----------------
#define BB   2
#define TT   1024
#define CC   768
#define HH   12
#define HD   64
#define LL   12
#define VV   50257
#define MM   (BB * TT)        // 2048 rows
#define LOG2E 1.4426950408889634f

// ---------------- Scratch (static device globals) ----------------
__device__ float g_x  [MM * CC];
__device__ float g_q  [MM * CC];                 // Q fp32 [B,T,C]
__device__ __align__(16) half g_kh[BB * HH * TT * HD];   // K hi [B,H,T,64]
__device__ __align__(16) half g_kl[BB * HH * TT * HD];
__device__ __align__(16) half g_vh[BB * HH * TT * HD];
__device__ __align__(16) half g_vl[BB * HH * TT * HD];
__device__ __align__(16) half g_ah[MM * CC];
__device__ __align__(16) half g_al[MM * CC];
__device__ __align__(16) half g_fh[MM * 4 * CC];
__device__ __align__(16) half g_fl[MM * 4 * CC];
// transposed weights, [N][K] K-major per layer, fp16 hi/lo split
__device__ __align__(16) half g_wqkv_h[LL * 3 * CC * CC];
__device__ __align__(16) half g_wqkv_l[LL * 3 * CC * CC];
__device__ __align__(16) half g_wproj_h[LL * CC * CC];
__device__ __align__(16) half g_wproj_l[LL * CC * CC];
__device__ __align__(16) half g_wfc_h [LL * 4 * CC * CC];
__device__ __align__(16) half g_wfc_l [LL * 4 * CC * CC];
__device__ __align__(16) half g_wfc2_h[LL * 4 * CC * CC];
__device__ __align__(16) half g_wfc2_l[LL * 4 * CC * CC];
// embedding table as fp16 (logits GEMM B operand, hi only)
__device__ __align__(16) half g_emb_h [VV * CC];

// ---------------- PTX helpers ----------------
__device__ __forceinline__ uint32_t smem_u32(const void* p) {
    uint32_t a;
    asm("{ .reg .u64 t; cvta.to.shared.u64 t, %1; cvt.u32.u64 %0, t; }"
        : "=r"(a) : "l"(p));
    return a;
}
__device__ __forceinline__ void cp16(uint32_t dst, const void* src, int srcsize) {
    asm volatile("cp.async.cg.shared.global [%0], [%1], 16, %2;"
                 :: "r"(dst), "l"(src), "r"(srcsize) : "memory");
}
__device__ __forceinline__ void ldm4(uint32_t r[4], uint32_t a) {
    asm volatile("ldmatrix.sync.aligned.m8n8.x4.shared.b16 {%0,%1,%2,%3}, [%4];"
                 : "=r"(r[0]), "=r"(r[1]), "=r"(r[2]), "=r"(r[3]) : "r"(a));
}
__device__ __forceinline__ void ldm4t(uint32_t r[4], uint32_t a) {
    asm volatile("ldmatrix.sync.aligned.m8n8.x4.trans.shared.b16 {%0,%1,%2,%3}, [%4];"
                 : "=r"(r[0]), "=r"(r[1]), "=r"(r[2]), "=r"(r[3]) : "r"(a));
}
__device__ __forceinline__ void mma16816h(float d[4], const uint32_t a[4],
                                          const uint32_t b[2]) {
    asm volatile(
        "mma.sync.aligned.m16n8k16.row.col.f32.f16.f16.f32 "
        "{%0,%1,%2,%3}, {%4,%5,%6,%7}, {%8,%9}, {%0,%1,%2,%3};"
        : "+f"(d[0]), "+f"(d[1]), "+f"(d[2]), "+f"(d[3])
        : "r"(a[0]), "r"(a[1]), "r"(a[2]), "r"(a[3]), "r"(b[0]), "r"(b[1]));
}
__device__ __forceinline__ float ex2(float x) {
    float y; asm("ex2.approx.ftz.f32 %0, %1;" : "=f"(y) : "f"(x)); return y;
}
__device__ __forceinline__ void pack_hl16(float f0, float f1, uint32_t& h, uint32_t& l) {
    half2 hv = __floats2half2_rn(f0, f1);
    half2 lv = __floats2half2_rn(f0 - __low2float(hv), f1 - __high2float(hv));
    h = *(uint32_t*)&hv; l = *(uint32_t*)&lv;
}

// ---------------- Prep: weight transpose/convert + embedding (one launch) --
__global__ __launch_bounds__(256)
void prep_all(const float* __restrict__ wq, const float* __restrict__ wp,
              const float* __restrict__ wf, const float* __restrict__ w2,
              half* __restrict__ qh, half* __restrict__ ql,
              half* __restrict__ ph, half* __restrict__ pl,
              half* __restrict__ fh, half* __restrict__ fl,
              half* __restrict__ h2, half* __restrict__ l2,
              const int* __restrict__ idx, const float* __restrict__ tok,
              const float* __restrict__ pos, float* __restrict__ x) {
    int z = blockIdx.z;
    if (z == LL * 4) {   // embedding job
        int id = blockIdx.y * 96 + blockIdx.x;
        if (id >= MM * CC / 256) return;
        int i = id * 256 + threadIdx.x;
        int c  = i % CC;
        int mt = i / CC;
        int t  = mt % TT;
        x[i] = tok[(long)idx[mt] * CC + c] + pos[t * CC + c];
        return;
    }
    int l = z >> 2, t = z & 3;
    int K = (t == 3) ? 4 * CC : CC;
    int N = (t == 0) ? 3 * CC : (t == 2) ? 4 * CC : CC;
    int n0 = blockIdx.x * 32, k0 = blockIdx.y * 32;
    if (n0 >= N || k0 >= K) return;
    const float* W;
    half *oh, *ol;
    if      (t == 0) { W = wq; oh = qh; ol = ql; }
    else if (t == 1) { W = wp; oh = ph; ol = pl; }
    else if (t == 2) { W = wf; oh = fh; ol = fl; }
    else             { W = w2; oh = h2; ol = l2; }
    long lofs = (long)l * K * N;

    __shared__ float tl[32][33];
    int tx = threadIdx.x & 31, ty = threadIdx.x >> 5;
    #pragma unroll
    for (int r = 0; r < 32; r += 8)
        tl[ty + r][tx] = W[lofs + (long)(k0 + ty + r) * N + n0 + tx];
    __syncthreads();
    #pragma unroll
    for (int r = 0; r < 32; r += 8) {
        int n = n0 + ty + r, k = k0 + tx;
        float v = tl[tx][ty + r];
        half h = __float2half_rn(v);
        long o = lofs + (long)n * K + k;
        oh[o] = h;
        ol[o] = __float2half_rn(v - __half2float(h));
    }
}

// ---------------- fp32 -> fp16 (hi only), float4 vectorized --------------
__global__ void cvt_act4h(const float4* __restrict__ in,
                          uint2* __restrict__ hi, int n4) {
    int i = blockIdx.x * blockDim.x + threadIdx.x;
    if (i >= n4) return;
    float4 v = in[i];
    half2 a = __floats2half2_rn(v.x, v.y);
    half2 b = __floats2half2_rn(v.z, v.w);
    hi[i] = make_uint2(*(uint32_t*)&a, *(uint32_t*)&b);
}

// ---------------- LayerNorm, warp-per-row -> fp16 hi/lo ----------------
__global__ __launch_bounds__(256)
void ln_kernel(const float* __restrict__ in,
               half* __restrict__ oh, half* __restrict__ ol,
               const float* __restrict__ w, const float* __restrict__ b) {
    int warp = threadIdx.x >> 5, lane = threadIdx.x & 31;
    int row = blockIdx.x * 8 + warp;
    const float* p = in + (long)row * CC;
    float4 v[6];
    float s = 0.f, s2 = 0.f;
    #pragma unroll
    for (int k = 0; k < 6; k++) {
        v[k] = *(const float4*)(p + lane * 4 + k * 128);
        s  += v[k].x + v[k].y + v[k].z + v[k].w;
        s2 += v[k].x * v[k].x + v[k].y * v[k].y + v[k].z * v[k].z + v[k].w * v[k].w;
    }
    #pragma unroll
    for (int o = 16; o > 0; o >>= 1) {
        s  += __shfl_xor_sync(0xffffffffu, s,  o);
        s2 += __shfl_xor_sync(0xffffffffu, s2, o);
    }
    float mean = s * (1.0f / CC);
    float var  = s2 * (1.0f / CC) - mean * mean;
    float inv  = rsqrtf(var + 1e-5f);
    #pragma unroll
    for (int k = 0; k < 6; k++) {
        int c = lane * 4 + k * 128;
        float4 wv = *(const float4*)(w + c);
        float4 bv = *(const float4*)(b + c);
        float o0 = (v[k].x - mean) * inv * wv.x + bv.x;
        float o1 = (v[k].y - mean) * inv * wv.y + bv.y;
        float o2 = (v[k].z - mean) * inv * wv.z + bv.z;
        float o3 = (v[k].w - mean) * inv * wv.w + bv.w;
        uint32_t ha, la, hb, lb;
        pack_hl16(o0, o1, ha, la);
        pack_hl16(o2, o3, hb, lb);
        long ofs = (long)row * CC + c;
        *(uint2*)(oh + ofs) = make_uint2(ha, hb);
        *(uint2*)(ol + ofs) = make_uint2(la, lb);
    }
}

// ---------------- LayerNorm -> fp16 hi only (final LN) ----------------
__global__ __launch_bounds__(256)
void ln_kernel_h(const float* __restrict__ in,
                 half* __restrict__ oh,
                 const float* __restrict__ w, const float* __restrict__ b) {
    int warp = threadIdx.x >> 5, lane = threadIdx.x & 31;
    int row = blockIdx.x * 8 + warp;
    const float* p = in + (long)row * CC;
    float4 v[6];
    float s = 0.f, s2 = 0.f;
    #pragma unroll
    for (int k = 0; k < 6; k++) {
        v[k] = *(const float4*)(p + lane * 4 + k * 128);
        s  += v[k].x + v[k].y + v[k].z + v[k].w;
        s2 += v[k].x * v[k].x + v[k].y * v[k].y + v[k].z * v[k].z + v[k].w * v[k].w;
    }
    #pragma unroll
    for (int o = 16; o > 0; o >>= 1) {
        s  += __shfl_xor_sync(0xffffffffu, s,  o);
        s2 += __shfl_xor_sync(0xffffffffu, s2, o);
    }
    float mean = s * (1.0f / CC);
    float var  = s2 * (1.0f / CC) - mean * mean;
    float inv  = rsqrtf(var + 1e-5f);
    #pragma unroll
    for (int k = 0; k < 6; k++) {
        int c = lane * 4 + k * 128;
        float4 wv = *(const float4*)(w + c);
        float4 bv = *(const float4*)(b + c);
        float o0 = (v[k].x - mean) * inv * wv.x + bv.x;
        float o1 = (v[k].y - mean) * inv * wv.y + bv.y;
        float o2 = (v[k].z - mean) * inv * wv.z + bv.z;
        float o3 = (v[k].w - mean) * inv * wv.w + bv.w;
        half2 a = __floats2half2_rn(o0, o1);
        half2 bq = __floats2half2_rn(o2, o3);
        long ofs = (long)row * CC + c;
        *(uint2*)(oh + ofs) = make_uint2(*(uint32_t*)&a, *(uint32_t*)&bq);
    }
}

// ---------------- Flash attention on tensor cores (split-fp16 3-pass) ----
#define ASTRIDE 144           // 72 elems per row (conflict-free ldmatrix)
#define TILE_B9 9216          // 64 * 144
#define ASTG    (4 * TILE_B9) // K_H,K_L,V_H,V_L per stage
#define ATT_SMEM (2 * ASTG)   // 73728

__global__ __launch_bounds__(128)
void attn_mma(const float* __restrict__ q,
              const half* __restrict__ kh, const half* __restrict__ kl,
              const half* __restrict__ vh, const half* __restrict__ vl,
              half* __restrict__ yh, half* __restrict__ yl) {
    extern __shared__ __align__(16) char sm[];
    uint32_t sb = smem_u32(sm);
    const uint32_t K_H = 0, K_L = TILE_B9, V_H = 2 * TILE_B9, V_L = 3 * TILE_B9;

    int qt = 15 - blockIdx.x;          // LPT: heavy tiles first
    int h = blockIdx.y, b = blockIdx.z;
    int tid = threadIdx.x, w = tid >> 5, lane = tid & 31;
    int q0 = qt * 64;
    const long kvofs = ((long)(b * HH + h) * TT) * HD;

    {
        int r = tid >> 1, d0 = (tid & 1) * 32;
        const float* qp = q + ((long)b * TT + q0 + r) * CC + h * HD + d0;
        const float qs = 0.125f * LOG2E;
        #pragma unroll
        for (int i = 0; i < 8; i++) {
            float4 v = *(const float4*)(qp + i * 4);
            uint32_t h0, l0, h1, l1;
            pack_hl16(v.x * qs, v.y * qs, h0, l0);
            pack_hl16(v.z * qs, v.w * qs, h1, l1);
            uint32_t o = r * ASTRIDE + (d0 + 4 * i) * 2;
            *(uint32_t*)(sm + K_H + o)     = h0;
            *(uint32_t*)(sm + K_H + o + 4) = h1;
            *(uint32_t*)(sm + K_L + o)     = l0;
            *(uint32_t*)(sm + K_L + o + 4) = l1;
        }
    }
    __syncthreads();
    uint32_t qh[4][4], ql[4][4];
    {
        uint32_t ao = (uint32_t)((w * 16 + (lane & 15)) * ASTRIDE + ((lane >> 4) << 4));
        #pragma unroll
        for (int kt = 0; kt < 4; kt++) {
            ldm4(qh[kt], sb + K_H + ao + kt * 32);
            ldm4(ql[kt], sb + K_L + ao + kt * 32);
        }
    }
    __syncthreads();

    int mat = lane >> 3;
    uint32_t bo = (uint32_t)((((mat >> 1) << 3) + (lane & 7)) * ASTRIDE + ((mat & 1) << 4));
    uint32_t vbo = (uint32_t)((((mat & 1) << 3) + (lane & 7)) * ASTRIDE + (((mat >> 1) << 3) << 1));

    auto load_tile = [&](int s, int c) {
        uint32_t st = sb + s * ASTG;
        long gb = kvofs + (long)c * 64 * HD;
        #pragma unroll
        for (int ch = tid; ch < 512; ch += 128) {
            int row = ch >> 3, c8 = ch & 7;
            uint32_t d = st + row * ASTRIDE + c8 * 16;
            long g = gb + row * HD + c8 * 8;
            cp16(d + K_H, kh + g, 16);
            cp16(d + K_L, kl + g, 16);
            cp16(d + V_H, vh + g, 16);
            cp16(d + V_L, vl + g, 16);
        }
    };

    float o_[8][4];
    #pragma unroll
    for (int nt = 0; nt < 8; nt++)
        #pragma unroll
        for (int e = 0; e < 4; e++) o_[nt][e] = 0.f;
    float m0r = -1e30f, m1r = -1e30f, l0s = 0.f, l1s = 0.f;

    load_tile(0, 0);
    asm volatile("cp.async.commit_group;" ::: "memory");
    if (qt >= 1) {
        load_tile(1, 1);
        asm volatile("cp.async.commit_group;" ::: "memory");
    }

    for (int kt0 = 0; kt0 <= qt; kt0++) {
        if (kt0 < qt)
            asm volatile("cp.async.wait_group 1;" ::: "memory");
        else
            asm volatile("cp.async.wait_group 0;" ::: "memory");
        __syncthreads();
        uint32_t st = sb + (kt0 & 1) * ASTG;

        float s[8][4];
        #pragma unroll
        for (int nt = 0; nt < 8; nt++)
            #pragma unroll
            for (int e = 0; e < 4; e++) s[nt][e] = 0.f;
        #pragma unroll
        for (int kt = 0; kt < 4; kt++) {
            #pragma unroll
            for (int jp = 0; jp < 4; jp++) {
                uint32_t t0[4], t1[4];
                uint32_t off = bo + kt * 32 + jp * (16 * ASTRIDE);
                ldm4(t0, st + K_H + off);
                ldm4(t1, st + K_L + off);
                uint32_t b0h[2] = {t0[0], t0[1]}, b1h[2] = {t0[2], t0[3]};
                uint32_t b0l[2] = {t1[0], t1[1]}, b1l[2] = {t1[2], t1[3]};
                mma16816h(s[2 * jp],     qh[kt], b0h);
                mma16816h(s[2 * jp],     qh[kt], b0l);
                mma16816h(s[2 * jp],     ql[kt], b0h);
                mma16816h(s[2 * jp + 1], qh[kt], b1h);
                mma16816h(s[2 * jp + 1], qh[kt], b1l);
                mma16816h(s[2 * jp + 1], ql[kt], b1h);
            }
        }

        if (kt0 == qt) {
            int rl0 = w * 16 + (lane >> 2);
            #pragma unroll
            for (int nt = 0; nt < 8; nt++) {
                int c = nt * 8 + (lane & 3) * 2;
                if (c > rl0)     s[nt][0] = -1e30f;
                if (c + 1 > rl0) s[nt][1] = -1e30f;
                if (c > rl0 + 8)     s[nt][2] = -1e30f;
                if (c + 1 > rl0 + 8) s[nt][3] = -1e30f;
            }
        }

        float mx0 = m0r, mx1 = m1r;
        #pragma unroll
        for (int nt = 0; nt < 8; nt++) {
            mx0 = fmaxf(mx0, fmaxf(s[nt][0], s[nt][1]));
            mx1 = fmaxf(mx1, fmaxf(s[nt][2], s[nt][3]));
        }
        mx0 = fmaxf(mx0, __shfl_xor_sync(0xffffffffu, mx0, 1));
        mx0 = fmaxf(mx0, __shfl_xor_sync(0xffffffffu, mx0, 2));
        mx1 = fmaxf(mx1, __shfl_xor_sync(0xffffffffu, mx1, 1));
        mx1 = fmaxf(mx1, __shfl_xor_sync(0xffffffffu, mx1, 2));
        float sc0 = ex2(m0r - mx0), sc1 = ex2(m1r - mx1);
        m0r = mx0; m1r = mx1;
        l0s *= sc0; l1s *= sc1;
        #pragma unroll
        for (int nt = 0; nt < 8; nt++) {
            o_[nt][0] *= sc0; o_[nt][1] *= sc0;
            o_[nt][2] *= sc1; o_[nt][3] *= sc1;
        }
        #pragma unroll
        for (int nt = 0; nt < 8; nt++) {
            s[nt][0] = ex2(s[nt][0] - mx0);
            s[nt][1] = ex2(s[nt][1] - mx0);
            s[nt][2] = ex2(s[nt][2] - mx1);
            s[nt][3] = ex2(s[nt][3] - mx1);
            l0s += s[nt][0] + s[nt][1];
            l1s += s[nt][2] + s[nt][3];
        }

        #pragma unroll
        for (int kt = 0; kt < 4; kt++) {
            uint32_t pah[4], pal[4];
            pack_hl16(s[2 * kt][0],     s[2 * kt][1],     pah[0], pal[0]);
            pack_hl16(s[2 * kt][2],     s[2 * kt][3],     pah[1], pal[1]);
            pack_hl16(s[2 * kt + 1][0], s[2 * kt + 1][1], pah[2], pal[2]);
            pack_hl16(s[2 * kt + 1][2], s[2 * kt + 1][3], pah[3], pal[3]);
            #pragma unroll
            for (int jp = 0; jp < 4; jp++) {
                uint32_t t0[4], t1[4];
                uint32_t off = vbo + kt * (16 * ASTRIDE) + jp * 32;
                ldm4t(t0, st + V_H + off);
                ldm4t(t1, st + V_L + off);
                uint32_t b0h[2] = {t0[0], t0[1]}, b1h[2] = {t0[2], t0[3]};
                uint32_t b0l[2] = {t1[0], t1[1]}, b1l[2] = {t1[2], t1[3]};
                mma16816h(o_[2 * jp],     pah, b0h);
                mma16816h(o_[2 * jp],     pah, b0l);
                mma16816h(o_[2 * jp],     pal, b0h);
                mma16816h(o_[2 * jp + 1], pah, b1h);
                mma16816h(o_[2 * jp + 1], pah, b1l);
                mma16816h(o_[2 * jp + 1], pal, b1h);
            }
        }
        __syncthreads();
        if (kt0 + 2 <= qt) {
            load_tile(kt0 & 1, kt0 + 2);
            asm volatile("cp.async.commit_group;" ::: "memory");
        }
    }

    l0s += __shfl_xor_sync(0xffffffffu, l0s, 1);
    l0s += __shfl_xor_sync(0xffffffffu, l0s, 2);
    l1s += __shfl_xor_sync(0xffffffffu, l1s, 1);
    l1s += __shfl_xor_sync(0xffffffffu, l1s, 2);
    float inv0 = 1.0f / l0s, inv1 = 1.0f / l1s;
    int r0 = q0 + w * 16 + (lane >> 2);
    #pragma unroll
    for (int nt = 0; nt < 8; nt++) {
        int d = nt * 8 + (lane & 3) * 2;
        long o0 = ((long)b * TT + r0) * CC + h * HD + d;
        long o1 = ((long)b * TT + r0 + 8) * CC + h * HD + d;
        uint32_t hv, lv;
        pack_hl16(o_[nt][0] * inv0, o_[nt][1] * inv0, hv, lv);
        *(uint32_t*)(yh + o0) = hv;
        *(uint32_t*)(yl + o0) = lv;
        pack_hl16(o_[nt][2] * inv1, o_[nt][3] * inv1, hv, lv);
        *(uint32_t*)(yh + o1) = hv;
        *(uint32_t*)(yl + o1) = lv;
    }
}

// ---------------- mma.sync split-fp16 GEMM, templated tile width ---------
// BM=64, BN in {128, 64}. Warp n-width = BN/4 (4 n-warps). BN=64 doubles
// CTA count for the N=768 GEMMs (proj/fc2) to fix wave quantization.
// EPI: 1 = +bias+residual fp32; 2 = +bias+GELU fp16 hi/lo;
//      3 = QKV split (Q fp32 [B,T,C], K/V fp16 hi/lo [B,H,T,64])
#define A_T64   9216              // 64 * 144

template<int EPI, int BN>
__global__ __launch_bounds__(256, 2)
void mma_gemm(const half* __restrict__ Ah, const half* __restrict__ Al,
              const half* __restrict__ Bh, const half* __restrict__ Bl,
              const float* __restrict__ bias, const float* __restrict__ res,
              float* __restrict__ C, half* __restrict__ Ch, half* __restrict__ Cl,
              half* __restrict__ Dh, half* __restrict__ Dl,
              int Ndim, int Kdim) {
    constexpr int B_T  = BN * 144;
    constexpr int STG  = 2 * A_T64 + 2 * B_T;
    constexpr int NT8  = BN / 32;      // n8-tiles per warp (128->4, 64->2)
    constexpr int JP   = NT8 / 2;      // ldmatrix pairs per kk
    constexpr int WNW  = BN / 4;       // warp n-width (32 or 16)  [FIXED]

    extern __shared__ char smemraw[];
    uint32_t sb = smem_u32(smemraw);
    int tid = threadIdx.x, w = tid >> 5, lane = tid & 31;
    int m0 = blockIdx.x * 64, n0 = blockIdx.y * BN;
    int wm = w >> 2, wn = w & 3;

    int mat = lane >> 3;
    const uint32_t aoff = (uint32_t)((wm * 32 + (lane & 15)) * 144 + ((lane >> 4) << 4));
    const uint32_t boff = (uint32_t)(2 * A_T64 +
        (wn * WNW + ((mat >> 1) << 3) + (lane & 7)) * 144 + ((mat & 1) << 4));

    float acc[2][NT8][4];
    #pragma unroll
    for (int i = 0; i < 2; i++)
        #pragma unroll
        for (int j = 0; j < NT8; j++)
            #pragma unroll
            for (int r = 0; r < 4; r++) acc[i][j][r] = 0.f;

    auto load_stage = [&](int slot, int c) {
        int k0 = c * 64;
        uint32_t st = sb + slot * STG;
        #pragma unroll
        for (int ch = tid; ch < 512; ch += 256) {
            int row = ch >> 3, c8 = ch & 7;
            const half* gh = Ah + (long)(m0 + row) * Kdim + k0 + c8 * 8;
            const half* gl = Al + (long)(m0 + row) * Kdim + k0 + c8 * 8;
            uint32_t d = st + row * 144 + c8 * 16;
            cp16(d, gh, 16);
            cp16(d + A_T64, gl, 16);
        }
        #pragma unroll
        for (int ch = tid; ch < BN * 8; ch += 256) {
            int row = ch >> 3, c8 = ch & 7;
            int n = n0 + row;
            int ok = (n < Ndim);
            int nn = ok ? n : 0;
            int ssz = ok ? 16 : 0;
            const half* gh = Bh + (long)nn * Kdim + k0 + c8 * 8;
            const half* gl = Bl + (long)nn * Kdim + k0 + c8 * 8;
            uint32_t d = st + 2 * A_T64 + row * 144 + c8 * 16;
            cp16(d, gh, ssz);
            cp16(d + B_T, gl, ssz);
        }
    };

    struct FragsT {
        uint32_t ah[2][4];
        uint32_t al[2][4];
        uint32_t bh[NT8][2];
        uint32_t bl[NT8][2];
    };

    auto ld_frags = [&](FragsT& f, uint32_t base, int kk) {
        uint32_t kof = (uint32_t)(kk * 32);
        #pragma unroll
        for (int i = 0; i < 2; i++) {
            uint32_t o = base + aoff + i * (16 * 144) + kof;
            ldm4(f.ah[i], o);
            ldm4(f.al[i], o + A_T64);
        }
        #pragma unroll
        for (int jp = 0; jp < JP; jp++) {
            uint32_t o = base + boff + jp * (16 * 144) + kof;
            uint32_t t0[4], t1[4];
            ldm4(t0, o);
            ldm4(t1, o + B_T);
            f.bh[2 * jp][0] = t0[0]; f.bh[2 * jp][1] = t0[1];
            f.bh[2 * jp + 1][0] = t0[2]; f.bh[2 * jp + 1][1] = t0[3];
            f.bl[2 * jp][0] = t1[0]; f.bl[2 * jp][1] = t1[1];
            f.bl[2 * jp + 1][0] = t1[2]; f.bl[2 * jp + 1][1] = t1[3];
        }
    };

    auto do_mma = [&](FragsT& f) {
        #pragma unroll
        for (int i = 0; i < 2; i++)
            #pragma unroll
            for (int j = 0; j < NT8; j++)
                mma16816h(acc[i][j], f.ah[i], f.bh[j]);
        #pragma unroll
        for (int i = 0; i < 2; i++)
            #pragma unroll
            for (int j = 0; j < NT8; j++)
                mma16816h(acc[i][j], f.ah[i], f.bl[j]);
        #pragma unroll
        for (int i = 0; i < 2; i++)
            #pragma unroll
            for (int j = 0; j < NT8; j++)
                mma16816h(acc[i][j], f.al[i], f.bh[j]);
    };

    const int NC = Kdim >> 6;

    load_stage(0, 0);
    asm volatile("cp.async.commit_group;" ::: "memory");
    load_stage(1, 1);
    asm volatile("cp.async.commit_group;" ::: "memory");
    asm volatile("cp.async.wait_group 1;" ::: "memory");
    __syncthreads();

    FragsT fr[2];
    ld_frags(fr[0], sb, 0);

    for (int c = 0; c < NC; c++) {
        uint32_t base = sb + (c & 1) * STG;
        #pragma unroll
        for (int kk = 0; kk < 4; kk++) {
            if (kk < 3) ld_frags(fr[(kk + 1) & 1], base, kk + 1);
            do_mma(fr[kk & 1]);
        }
        __syncthreads();
        if (c + 2 < NC) {
            load_stage(c & 1, c + 2);
            asm volatile("cp.async.commit_group;" ::: "memory");
        }
        if (c + 1 < NC) {
            if (c + 2 < NC)
                asm volatile("cp.async.wait_group 1;" ::: "memory");
            else
                asm volatile("cp.async.wait_group 0;" ::: "memory");
            __syncthreads();
            ld_frags(fr[0], sb + ((c + 1) & 1) * STG, 0);
        }
    }

    if (EPI == 3) {
        // QKV: Q -> fp32 [B,T,C]; K,V -> fp16 hi/lo [B,H,T,64]
        #pragma unroll
        for (int i = 0; i < 2; i++) {
            int row0 = m0 + wm * 32 + i * 16 + (lane >> 2);
            #pragma unroll
            for (int j = 0; j < NT8; j++) {
                int col = n0 + wn * WNW + j * 8 + 2 * (lane & 3);
                float b0 = __ldg(bias + col), b1 = __ldg(bias + col + 1);
                int region = col / CC;      // 0=Q, 1=K, 2=V
                int cm = col % CC;
                int hh = cm >> 6, d = cm & 63;
                #pragma unroll
                for (int h2 = 0; h2 < 2; h2++) {
                    int rr = row0 + h2 * 8;
                    float f0 = acc[i][j][h2 * 2] + b0;
                    float f1 = acc[i][j][h2 * 2 + 1] + b1;
                    if (region == 0) {
                        C[(long)rr * CC + cm]     = f0;
                        C[(long)rr * CC + cm + 1] = f1;
                    } else {
                        int bb = rr >> 10, tt = rr & 1023;
                        long o = ((long)(bb * HH + hh) * TT + tt) * HD + d;
                        uint32_t hv, lv;
                        pack_hl16(f0, f1, hv, lv);
                        if (region == 1) {
                            *(uint32_t*)(Ch + o) = hv;
                            *(uint32_t*)(Cl + o) = lv;
                        } else {
                            *(uint32_t*)(Dh + o) = hv;
                            *(uint32_t*)(Dl + o) = lv;
                        }
                    }
                }
            }
        }
        return;
    }

    #pragma unroll
    for (int i = 0; i < 2; i++) {
        int row0 = m0 + wm * 32 + i * 16 + (lane >> 2);
        #pragma unroll
        for (int j = 0; j < NT8; j++) {
            int col = n0 + wn * WNW + j * 8 + 2 * (lane & 3);
            #pragma unroll
            for (int r = 0; r < 4; r++) {
                int rr = row0 + (r >> 1) * 8;
                int cc = col + (r & 1);
                if (cc < Ndim) {
                    float v = acc[i][j][r];
                    if (bias) v += __ldg(bias + cc);
                    long o = (long)rr * Ndim + cc;
                    if (EPI == 1) v += res[o];
                    if (EPI == 2) {
                        v = 0.5f * v * (1.f + erff(v * 0.70710678118654752f));
                        half hh = __float2half_rn(v);
                        Ch[o] = hh;
                        Cl[o] = __float2half_rn(v - __half2float(hh));
                    } else {
                        C[o] = v;
                    }
                }
            }
        }
    }
}

#define GEMM_SMEM_128 (2 * (2 * A_T64 + 2 * 128 * 144))   // 110592
#define GEMM_SMEM_64  (2 * (2 * A_T64 + 2 * 64 * 144))    // 73728

// ---------------- fp16 1-pass GEMM (logits only) ----------------
#define B_T128  18432
#define STAGE_H1 (A_T64 + B_T128)          // 27648
#define GEMM_SMEM_H1 (2 * STAGE_H1)        // 55296

__global__ __launch_bounds__(256, 2)
void mma_gemm_h1(const half* __restrict__ Ah, const half* __restrict__ Bh,
                 float* __restrict__ C, int Ndim, int Kdim) {
    extern __shared__ char smemraw[];
    uint32_t sb = smem_u32(smemraw);
    int tid = threadIdx.x, w = tid >> 5, lane = tid & 31;
    int m0 = blockIdx.x * 64, n0 = blockIdx.y * 128;
    int wm = w >> 2, wn = w & 3;

    int mat = lane >> 3;
    const uint32_t aoff = (uint32_t)((wm * 32 + (lane & 15)) * 144 + ((lane >> 4) << 4));
    const uint32_t boff = (uint32_t)(A_T64 +
        (wn * 32 + ((mat >> 1) << 3) + (lane & 7)) * 144 + ((mat & 1) << 4));

    float acc[2][4][4];
    #pragma unroll
    for (int i = 0; i < 2; i++)
        #pragma unroll
        for (int j = 0; j < 4; j++)
            #pragma unroll
            for (int r = 0; r < 4; r++) acc[i][j][r] = 0.f;

    auto load_stage = [&](int slot, int c) {
        int k0 = c * 64;
        uint32_t st = sb + slot * STAGE_H1;
        #pragma unroll
        for (int ch = tid; ch < 512; ch += 256) {
            int row = ch >> 3, c8 = ch & 7;
            const half* gh = Ah + (long)(m0 + row) * Kdim + k0 + c8 * 8;
            cp16(st + row * 144 + c8 * 16, gh, 16);
        }
        #pragma unroll
        for (int ch = tid; ch < 1024; ch += 256) {
            int row = ch >> 3, c8 = ch & 7;
            int n = n0 + row;
            int ok = (n < Ndim);
            int nn = ok ? n : 0;
            int ssz = ok ? 16 : 0;
            const half* gh = Bh + (long)nn * Kdim + k0 + c8 * 8;
            cp16(st + A_T64 + row * 144 + c8 * 16, gh, ssz);
        }
    };

    const int NC = Kdim >> 6;

    load_stage(0, 0);
    asm volatile("cp.async.commit_group;" ::: "memory");
    load_stage(1, 1);
    asm volatile("cp.async.commit_group;" ::: "memory");

    for (int c = 0; c < NC; c++) {
        if (c + 1 < NC)
            asm volatile("cp.async.wait_group 1;" ::: "memory");
        else
            asm volatile("cp.async.wait_group 0;" ::: "memory");
        __syncthreads();

        uint32_t base = sb + (c & 1) * STAGE_H1;
        #pragma unroll
        for (int kk = 0; kk < 4; kk++) {
            uint32_t kof = (uint32_t)(kk * 32);
            uint32_t ah[2][4], bh[4][2];
            #pragma unroll
            for (int i = 0; i < 2; i++)
                ldm4(ah[i], base + aoff + i * (16 * 144) + kof);
            #pragma unroll
            for (int jp = 0; jp < 2; jp++) {
                uint32_t t0[4];
                ldm4(t0, base + boff + jp * (16 * 144) + kof);
                bh[2 * jp][0] = t0[0]; bh[2 * jp][1] = t0[1];
                bh[2 * jp + 1][0] = t0[2]; bh[2 * jp + 1][1] = t0[3];
            }
            #pragma unroll
            for (int i = 0; i < 2; i++)
                #pragma unroll
                for (int j = 0; j < 4; j++)
                    mma16816h(acc[i][j], ah[i], bh[j]);
        }
        __syncthreads();
        if (c + 2 < NC) {
            load_stage(c & 1, c + 2);
            asm volatile("cp.async.commit_group;" ::: "memory");
        }
    }

    #pragma unroll
    for (int i = 0; i < 2; i++) {
        int row0 = m0 + wm * 32 + i * 16 + (lane >> 2);
        #pragma unroll
        for (int j = 0; j < 4; j++) {
            int col = n0 + wn * 32 + j * 8 + 2 * (lane & 3);
            #pragma unroll
            for (int r = 0; r < 4; r++) {
                int rr = row0 + (r >> 1) * 8;
                int cc = col + (r & 1);
                if (cc < Ndim)
                    C[(long)rr * Ndim + cc] = acc[i][j][r];
            }
        }
    }
}

// ---------------- Host orchestration ----------------
extern "C" void kernel_launch(void* const* d_in, const int* in_sizes, int n_in,
                              void* d_out, int out_size) {
    const int*   idx     = (const int*)  d_in[0];
    const float* tok_emb = (const float*)d_in[1];
    const float* pos_emb = (const float*)d_in[2];
    const float* ln1_w   = (const float*)d_in[3];
    const float* ln1_b   = (const float*)d_in[4];
    const float* w_qkv   = (const float*)d_in[5];
    const float* b_qkv   = (const float*)d_in[6];
    const float* w_proj  = (const float*)d_in[7];
    const float* b_proj  = (const float*)d_in[8];
    const float* ln2_w   = (const float*)d_in[9];
    const float* ln2_b   = (const float*)d_in[10];
    const float* w_fc    = (const float*)d_in[11];
    const float* b_fc    = (const float*)d_in[12];
    const float* w_fc2   = (const float*)d_in[13];
    const float* b_fc2   = (const float*)d_in[14];
    const float* lnf_w   = (const float*)d_in[15];
    const float* lnf_b   = (const float*)d_in[16];
    float* out = (float*)d_out;

    cudaFuncSetAttribute(mma_gemm<1, 64>,  cudaFuncAttributeMaxDynamicSharedMemorySize, GEMM_SMEM_64);
    cudaFuncSetAttribute(mma_gemm<2, 128>, cudaFuncAttributeMaxDynamicSharedMemorySize, GEMM_SMEM_128);
    cudaFuncSetAttribute(mma_gemm<3, 128>, cudaFuncAttributeMaxDynamicSharedMemorySize, GEMM_SMEM_128);
    cudaFuncSetAttribute(mma_gemm_h1,      cudaFuncAttributeMaxDynamicSharedMemorySize, GEMM_SMEM_H1);
    cudaFuncSetAttribute(attn_mma,         cudaFuncAttributeMaxDynamicSharedMemorySize, ATT_SMEM);

    float *x, *q;
    cudaGetSymbolAddress((void**)&x, g_x);
    cudaGetSymbolAddress((void**)&q, g_q);
    half *kh, *kl, *vh, *vl, *ah, *al, *fh, *fl;
    half *wqh, *wql, *wph, *wpl, *wfh, *wfl, *w2h, *w2l, *eh;
    cudaGetSymbolAddress((void**)&kh,  g_kh);      cudaGetSymbolAddress((void**)&kl,  g_kl);
    cudaGetSymbolAddress((void**)&vh,  g_vh);      cudaGetSymbolAddress((void**)&vl,  g_vl);
    cudaGetSymbolAddress((void**)&ah,  g_ah);      cudaGetSymbolAddress((void**)&al,  g_al);
    cudaGetSymbolAddress((void**)&fh,  g_fh);      cudaGetSymbolAddress((void**)&fl,  g_fl);
    cudaGetSymbolAddress((void**)&wqh, g_wqkv_h);  cudaGetSymbolAddress((void**)&wql, g_wqkv_l);
    cudaGetSymbolAddress((void**)&wph, g_wproj_h); cudaGetSymbolAddress((void**)&wpl, g_wproj_l);
    cudaGetSymbolAddress((void**)&wfh, g_wfc_h);   cudaGetSymbolAddress((void**)&wfl, g_wfc_l);
    cudaGetSymbolAddress((void**)&w2h, g_wfc2_h);  cudaGetSymbolAddress((void**)&w2l, g_wfc2_l);
    cudaGetSymbolAddress((void**)&eh,  g_emb_h);

    // #1: weight prep + embedding; #2: emb-table fp16 convert
    prep_all<<<dim3(96, 96, LL * 4 + 1), 256>>>(w_qkv, w_proj, w_fc, w_fc2,
                                                wqh, wql, wph, wpl,
                                                wfh, wfl, w2h, w2l,
                                                idx, tok_emb, pos_emb, x);
    {
        int n4 = VV * CC / 4;
        cvt_act4h<<<(n4 + 255) / 256, 256>>>((const float4*)tok_emb,
                                             (uint2*)eh, n4);
    }

    for (int l = 0; l < LL; l++) {
        // LN1 -> QKV GEMM: Q fp32, K/V fp16 hi/lo pre-converted
        ln_kernel<<<MM / 8, 256>>>(x, ah, al, ln1_w + (long)l * CC, ln1_b + (long)l * CC);
        mma_gemm<3, 128><<<dim3(MM / 64, 3 * CC / 128), 256, GEMM_SMEM_128>>>(
            ah, al, wqh + (long)l * 3 * CC * CC, wql + (long)l * 3 * CC * CC,
            b_qkv + (long)l * 3 * CC, nullptr, q, kh, kl, vh, vl, 3 * CC, CC);
        // attention (tensor-core flash) -> fp16 hi/lo
        attn_mma<<<dim3(16, HH, BB), 128, ATT_SMEM>>>(q, kh, kl, vh, vl, ah, al);
        // proj + residual -> x   (BN=64: 384 CTAs, balanced waves)
        mma_gemm<1, 64><<<dim3(MM / 64, CC / 64), 256, GEMM_SMEM_64>>>(
            ah, al, wph + (long)l * CC * CC, wpl + (long)l * CC * CC,
            b_proj + (long)l * CC, x, x, nullptr, nullptr, nullptr, nullptr, CC, CC);
        // LN2 -> FC1 + GELU -> fp16 hi/lo
        ln_kernel<<<MM / 8, 256>>>(x, ah, al, ln2_w + (long)l * CC, ln2_b + (long)l * CC);
        mma_gemm<2, 128><<<dim3(MM / 64, 4 * CC / 128), 256, GEMM_SMEM_128>>>(
            ah, al, wfh + (long)l * 4 * CC * CC, wfl + (long)l * 4 * CC * CC,
            b_fc + (long)l * 4 * CC, nullptr, nullptr, fh, fl, nullptr, nullptr, 4 * CC, CC);
        // FC2 + residual -> x   (BN=64: 384 CTAs, balanced waves)
        mma_gemm<1, 64><<<dim3(MM / 64, CC / 64), 256, GEMM_SMEM_64>>>(
            fh, fl, w2h + (long)l * 4 * CC * CC, w2l + (long)l * 4 * CC * CC,
            b_fc2 + (long)l * CC, x, x, nullptr, nullptr, nullptr, nullptr, CC, 4 * CC);
    }

    // final LN (fp16 hi only) + tied head via fp16 1-pass GEMM
    ln_kernel_h<<<MM / 8, 256>>>(x, (half*)ah, lnf_w, lnf_b);
    mma_gemm_h1<<<dim3(MM / 64, (VV + 127) / 128), 256, GEMM_SMEM_H1>>>(
        (half*)ah, eh, out, VV, CC);
}